// round 13
// baseline (speedup 1.0000x reference)
#include <cuda_runtime.h>
#include <cuda_fp16.h>
#include <cstdint>

// Problem constants (B=2, S=4096, D=2048, E=8, DFF=8192, TOP_K=2)
#define NTOK   8192
#define DMODEL 2048
#define NEXP   8
#define FFDIM  8192
#define TOPK   2

// ---------------- device scratch (allocation-free rule: __device__ globals) --
__device__ float  g_logits[NTOK * NEXP];
__device__ float  g_sums[NEXP];
__device__ int    g_sel[TOPK];
__device__ float  g_rw[NTOK * TOPK];
__device__ __half g_xh[(size_t)NTOK * DMODEL];        // x  fp16 [M,K]
__device__ __half g_h0[(size_t)NTOK * FFDIM];         // h expert0 fp16 [M,K]
__device__ __half g_h1[(size_t)NTOK * FFDIM];         // h expert1 fp16 [M,K]
__device__ __half g_w1t[2][(size_t)FFDIM * DMODEL];   // w1^T fp16 [N=FF, K=D]
__device__ __half g_w2t[2][(size_t)DMODEL * FFDIM];   // w2^T fp16 [N=D,  K=FF]

// ---------------- helpers ----------------------------------------------------
__device__ __forceinline__ void cp16(void* smem, const void* gmem) {
    uint32_t s = (uint32_t)__cvta_generic_to_shared(smem);
    asm volatile("cp.async.cg.shared.global [%0], [%1], 16;\n" :: "r"(s), "l"(gmem));
}
__device__ __forceinline__ void cp_commit() {
    asm volatile("cp.async.commit_group;\n" ::: "memory");
}
template <int N>
__device__ __forceinline__ void cp_wait() {
    asm volatile("cp.async.wait_group %0;\n" :: "n"(N) : "memory");
}
__device__ __forceinline__ void ldsm4(uint32_t* r, uint32_t addr) {
    asm volatile("ldmatrix.sync.aligned.m8n8.x4.shared.b16 {%0,%1,%2,%3}, [%4];"
                 : "=r"(r[0]), "=r"(r[1]), "=r"(r[2]), "=r"(r[3]) : "r"(addr));
}

// ---------------- routing kernels -------------------------------------------
__global__ void router_kernel(const float* __restrict__ x,
                              const float* __restrict__ gw) {
    int n = blockIdx.x;
    const float* xr = x + (size_t)n * DMODEL;
    float acc[NEXP];
#pragma unroll
    for (int e = 0; e < NEXP; e++) acc[e] = 0.f;
    for (int d = threadIdx.x; d < DMODEL; d += 256) {
        float xv = xr[d];
#pragma unroll
        for (int e = 0; e < NEXP; e++)
            acc[e] = fmaf(xv, gw[e * DMODEL + d], acc[e]);
    }
#pragma unroll
    for (int e = 0; e < NEXP; e++)
#pragma unroll
        for (int off = 16; off; off >>= 1)
            acc[e] += __shfl_xor_sync(0xffffffffu, acc[e], off);

    __shared__ float red[NEXP][8];
    int w = threadIdx.x >> 5, lane = threadIdx.x & 31;
    if (lane == 0) {
#pragma unroll
        for (int e = 0; e < NEXP; e++) red[e][w] = acc[e];
    }
    __syncthreads();
    if (threadIdx.x < NEXP) {
        float s = 0.f;
#pragma unroll
        for (int ww = 0; ww < 8; ww++) s += red[threadIdx.x][ww];
        g_logits[n * NEXP + threadIdx.x] = s;
    }
}

__global__ void sum_kernel() {
    int e = blockIdx.x;
    float s = 0.f;
    for (int n = threadIdx.x; n < NTOK; n += blockDim.x)
        s += g_logits[n * NEXP + e];
    __shared__ float sm[256];
    sm[threadIdx.x] = s;
    __syncthreads();
    for (int off = 128; off; off >>= 1) {
        if (threadIdx.x < off) sm[threadIdx.x] += sm[threadIdx.x + off];
        __syncthreads();
    }
    if (threadIdx.x == 0) g_sums[e] = sm[0];
}

__global__ void topk_kernel() {
    if (threadIdx.x == 0) {
        int b = 0;
        for (int i = 1; i < NEXP; i++)
            if (g_sums[i] > g_sums[b]) b = i;     // strict > : lower idx on tie
        int s = (b == 0) ? 1 : 0;
        for (int i = 0; i < NEXP; i++)
            if (i != b && g_sums[i] > g_sums[s]) s = i;
        g_sel[0] = b;
        g_sel[1] = s;
    }
}

__global__ void rw_kernel() {
    int n = blockIdx.x * blockDim.x + threadIdx.x;
    if (n >= NTOK) return;
    int s0 = g_sel[0], s1 = g_sel[1];
    float l0 = g_logits[n * NEXP + s0];
    float l1 = g_logits[n * NEXP + s1];
    float m  = fmaxf(l0, l1);
    float e0 = expf(l0 - m), e1 = expf(l1 - m);
    float inv = 1.0f / (e0 + e1);
    g_rw[n * TOPK + 0] = e0 * inv;
    g_rw[n * TOPK + 1] = e1 * inv;
}

// fp32 -> fp16 straight convert (x)
__global__ void cvt_x_h(const float4* __restrict__ src,
                        __half2* __restrict__ dst, size_t n4) {
    for (size_t i = (size_t)blockIdx.x * blockDim.x + threadIdx.x; i < n4;
         i += (size_t)gridDim.x * blockDim.x) {
        float4 v = src[i];
        dst[i * 2 + 0] = __floats2half2_rn(v.x, v.y);
        dst[i * 2 + 1] = __floats2half2_rn(v.z, v.w);
    }
}

// Transpose + fp16-convert selected expert weight: in [K,N] fp32 -> out [N,K] fp16
__global__ void transpose_cvt_h(const float* __restrict__ Wall,
                                __half* __restrict__ out,
                                int kidx, int K, int N) {
    __shared__ float t[32][33];
    int e = g_sel[kidx];
    const float* src = Wall + (size_t)e * K * N;
    int n0 = blockIdx.x * 32, k0 = blockIdx.y * 32;
#pragma unroll
    for (int i = threadIdx.y; i < 32; i += 8)
        t[i][threadIdx.x] = src[(size_t)(k0 + i) * N + n0 + threadIdx.x];
    __syncthreads();
#pragma unroll
    for (int i = threadIdx.y; i < 32; i += 8)
        out[(size_t)(n0 + i) * K + k0 + threadIdx.x] = __float2half_rn(t[threadIdx.x][i]);
}

// ---------------- fp16 GEMM: BMTx256 CTA, ldmatrix + cp.async 4-stage --------
#define BN 256
#define BK 32
#define ASTRH 40    // halves per row (BK+8): 80B stride; 16B-aligned, ldsm conflict-free
#define BSTRH 40
#define NSTAGE 4
#define B_TILE_H (BN * BSTRH)

__device__ __forceinline__ void mma_f16(float* c, const uint32_t* a, const uint32_t* b) {
    asm volatile(
        "mma.sync.aligned.m16n8k16.row.col.f32.f16.f16.f32 "
        "{%0,%1,%2,%3}, {%4,%5,%6,%7}, {%8,%9}, {%0,%1,%2,%3};\n"
        : "+f"(c[0]), "+f"(c[1]), "+f"(c[2]), "+f"(c[3])
        : "r"(a[0]), "r"(a[1]), "r"(a[2]), "r"(a[3]), "r"(b[0]), "r"(b[1]));
}

__device__ __forceinline__ float gelu_tanh(float x) {
    float x3 = x * x * x;
    float t  = tanhf(0.7978845608028654f * (x + 0.044715f * x3));
    return 0.5f * x * (1.0f + t);
}

// MODE 0: Ch = fp16(gelu(A@B^T + bias))      (h production, C is __half*)
// MODE 1: Cf = rw[:,kidx] * (A@B^T + bias)   (C is float*)
// MODE 2: Cf += rw[:,kidx] * (A@B^T + bias)
template <int MODE, int BMT>
__global__ void __launch_bounds__(256, 1)
moe_gemm_h(const __half* __restrict__ A,      // [M,K] fp16
           const __half* __restrict__ Bt,     // [N,K] fp16
           const float* __restrict__ Ball,    // bias table [E,N] fp32
           int kidx, int N, int K,
           void* __restrict__ Cv) {
    constexpr int MT = BMT / 32;              // m16 tiles per warp
    constexpr int A_TILE_H = BMT * ASTRH;
    extern __shared__ __half smh[];
    __half* As = smh;                          // NSTAGE * A_TILE_H
    __half* Bs = smh + NSTAGE * A_TILE_H;      // NSTAGE * B_TILE_H

    const int tid  = threadIdx.x;
    const int lane = tid & 31;
    const int wid  = tid >> 5;
    const int g    = lane >> 2;     // 0..7
    const int tg   = lane & 3;      // 0..3
    const int wm   = wid & 1;       // BMT/2 rows each
    const int wn   = wid >> 1;      // 64 cols each
    const int m0   = blockIdx.y * BMT;
    const int n0   = blockIdx.x * BN;

    const int e = g_sel[kidx];
    const float* bias = Ball + (size_t)e * N;

    // ldmatrix per-lane base byte-offsets (kk = 0)
    const int lr  = lane & 7;
    const int sel = lane >> 3;      // 0..3
    uint32_t aoff[MT], boff[4];
#pragma unroll
    for (int mt = 0; mt < MT; mt++) {
        int row = wm * (BMT / 2) + mt * 16 + (sel & 1) * 8 + lr;
        aoff[mt] = (uint32_t)(row * ASTRH + (sel >> 1) * 8) * 2;
    }
#pragma unroll
    for (int p = 0; p < 4; p++) {
        int nn = wn * 64 + p * 16 + (sel >> 1) * 8 + lr;
        boff[p] = (uint32_t)(nn * BSTRH + (sel & 1) * 8) * 2;
    }
    const uint32_t As_u = (uint32_t)__cvta_generic_to_shared(As);
    const uint32_t Bs_u = (uint32_t)__cvta_generic_to_shared(Bs);

    float acc[MT][8][4];
#pragma unroll
    for (int i = 0; i < MT; i++)
#pragma unroll
        for (int j = 0; j < 8; j++)
#pragma unroll
            for (int r = 0; r < 4; r++) acc[i][j][r] = 0.f;

    const int KT = K / BK;

    auto issue_stage = [&](int s, int kt) {
        const int k0 = kt * BK;
        __half* as = As + s * A_TILE_H;
        __half* bs = Bs + s * B_TILE_H;
#pragma unroll
        for (int i = 0; i < BMT / 64; i++) {       // A: BMT*4 chunks
            int idx = tid + i * 256;
            int r = idx >> 2, ch = idx & 3;
            cp16(&as[r * ASTRH + ch * 8], A + (size_t)(m0 + r) * K + k0 + ch * 8);
        }
#pragma unroll
        for (int i = 0; i < 4; i++) {              // B: 1024 chunks
            int idx = tid + i * 256;
            int r = idx >> 2, ch = idx & 3;
            cp16(&bs[r * BSTRH + ch * 8], Bt + (size_t)(n0 + r) * K + k0 + ch * 8);
        }
    };

    // prologue: stages 0..2
    issue_stage(0, 0); cp_commit();
    if (KT > 1) issue_stage(1, 1);
    cp_commit();
    if (KT > 2) issue_stage(2, 2);
    cp_commit();

    for (int kt = 0; kt < KT; kt++) {
        cp_wait<2>();
        __syncthreads();

        if (kt + 3 < KT) issue_stage((kt + 3) & (NSTAGE - 1), kt + 3);
        cp_commit();

        const uint32_t a_base = As_u + (uint32_t)((kt & (NSTAGE - 1)) * A_TILE_H) * 2;
        const uint32_t b_base = Bs_u + (uint32_t)((kt & (NSTAGE - 1)) * B_TILE_H) * 2;

#pragma unroll
        for (int ks = 0; ks < 2; ks++) {
            const uint32_t ko = ks * 32;          // +16 halves
            uint32_t af[MT][4], bq[4][4];
#pragma unroll
            for (int mt = 0; mt < MT; mt++) ldsm4(af[mt], a_base + aoff[mt] + ko);
#pragma unroll
            for (int p = 0; p < 4; p++)  ldsm4(bq[p],  b_base + boff[p] + ko);
#pragma unroll
            for (int mt = 0; mt < MT; mt++)
#pragma unroll
                for (int nt = 0; nt < 8; nt++)
                    mma_f16(acc[mt][nt], af[mt], &bq[nt >> 1][(nt & 1) * 2]);
        }
        // next iteration's __syncthreads() protects the stage being overwritten
    }

    // ---------------- epilogue ----------------
#pragma unroll
    for (int mt = 0; mt < MT; mt++) {
        int r0 = m0 + wm * (BMT / 2) + mt * 16 + g;
        float w0 = 0.f, w1 = 0.f;
        if (MODE != 0) {
            w0 = g_rw[(size_t)r0 * TOPK + kidx];
            w1 = g_rw[(size_t)(r0 + 8) * TOPK + kidx];
        }
#pragma unroll
        for (int nt = 0; nt < 8; nt++) {
            int cc = n0 + wn * 64 + nt * 8 + tg * 2;
            const float* cr = acc[mt][nt];
            float b0 = bias[cc], b1v = bias[cc + 1];
            float y00 = cr[0] + b0, y01 = cr[1] + b1v;
            float y10 = cr[2] + b0, y11 = cr[3] + b1v;
            if (MODE == 0) {
                __half* C = (__half*)Cv;
                __half2* p0 = (__half2*)(C + (size_t)r0 * N + cc);
                __half2* p1 = (__half2*)(C + (size_t)(r0 + 8) * N + cc);
                *p0 = __floats2half2_rn(gelu_tanh(y00), gelu_tanh(y01));
                *p1 = __floats2half2_rn(gelu_tanh(y10), gelu_tanh(y11));
            } else {
                float* C = (float*)Cv;
                float* p0 = C + (size_t)r0 * N + cc;
                float* p1 = C + (size_t)(r0 + 8) * N + cc;
                if (MODE == 1) {
                    float2 o0 = {w0 * y00, w0 * y01};
                    float2 o1 = {w1 * y10, w1 * y11};
                    *reinterpret_cast<float2*>(p0) = o0;
                    *reinterpret_cast<float2*>(p1) = o1;
                } else {
                    float2 c0 = *reinterpret_cast<float2*>(p0);
                    float2 c1 = *reinterpret_cast<float2*>(p1);
                    c0.x += w0 * y00; c0.y += w0 * y01;
                    c1.x += w1 * y10; c1.y += w1 * y11;
                    *reinterpret_cast<float2*>(p0) = c0;
                    *reinterpret_cast<float2*>(p1) = c1;
                }
            }
        }
    }
}

#define SMEM_G1 (NSTAGE * (128 * ASTRH + B_TILE_H) * 2)
#define SMEM_G2 (NSTAGE * (64 * ASTRH + B_TILE_H) * 2)

// ---------------- launch -----------------------------------------------------
extern "C" void kernel_launch(void* const* d_in, const int* in_sizes, int n_in,
                              void* d_out, int out_size) {
    const float* x  = (const float*)d_in[0];   // [8192,2048]
    const float* gw = (const float*)d_in[1];   // [8,2048]
    const float* w1 = (const float*)d_in[2];   // [8,2048,8192]
    const float* b1 = (const float*)d_in[3];   // [8,8192]
    const float* w2 = (const float*)d_in[4];   // [8,8192,2048]
    const float* b2 = (const float*)d_in[5];   // [8,2048]
    float* out = (float*)d_out;                // [8192,2048]

    __half *xh, *h0, *h1, *w1t0, *w2t0;
    cudaGetSymbolAddress((void**)&xh,   g_xh);
    cudaGetSymbolAddress((void**)&h0,   g_h0);
    cudaGetSymbolAddress((void**)&h1,   g_h1);
    cudaGetSymbolAddress((void**)&w1t0, g_w1t);
    cudaGetSymbolAddress((void**)&w2t0, g_w2t);
    __half* w1t1 = w1t0 + (size_t)FFDIM * DMODEL;
    __half* w2t1 = w2t0 + (size_t)DMODEL * FFDIM;

    static bool s_init = false;
    static cudaStream_t s1;
    static cudaEvent_t ev_pre, ev_e1g1;
    if (!s_init) {
        cudaStreamCreateWithFlags(&s1, cudaStreamNonBlocking);
        cudaEventCreateWithFlags(&ev_pre,  cudaEventDisableTiming);
        cudaEventCreateWithFlags(&ev_e1g1, cudaEventDisableTiming);
        cudaFuncSetAttribute((const void*)moe_gemm_h<0, 128>,
                             cudaFuncAttributeMaxDynamicSharedMemorySize, SMEM_G1);
        cudaFuncSetAttribute((const void*)moe_gemm_h<1, 64>,
                             cudaFuncAttributeMaxDynamicSharedMemorySize, SMEM_G2);
        cudaFuncSetAttribute((const void*)moe_gemm_h<2, 64>,
                             cudaFuncAttributeMaxDynamicSharedMemorySize, SMEM_G2);
        s_init = true;
    }

    // ---- routing + operand prep (default stream) ----
    router_kernel<<<NTOK, 256>>>(x, gw);
    sum_kernel<<<NEXP, 256>>>();
    topk_kernel<<<1, 32>>>();
    rw_kernel<<<NTOK / 256, 256>>>();

    cvt_x_h<<<2048, 256>>>((const float4*)x, (__half2*)xh, ((size_t)NTOK * DMODEL) >> 2);
    dim3 tb(32, 8);
    dim3 tg1(FFDIM / 32, DMODEL / 32);   // w1: K=2048, N=8192
    dim3 tg2(DMODEL / 32, FFDIM / 32);   // w2: K=8192, N=2048
    transpose_cvt_h<<<tg1, tb>>>(w1, w1t0, 0, DMODEL, FFDIM);
    transpose_cvt_h<<<tg1, tb>>>(w1, w1t1, 1, DMODEL, FFDIM);

    // fork: expert1 GEMM1 runs on s1 concurrently with the rest of stream 0
    cudaEventRecord(ev_pre, 0);
    cudaStreamWaitEvent(s1, ev_pre, 0);

    dim3 blk(256);
    dim3 gg1(FFDIM / BN, NTOK / 128);   // (32,64)
    dim3 gg2(DMODEL / BN, NTOK / 64);   // (8,128)

    moe_gemm_h<0, 128><<<gg1, blk, SMEM_G1, s1>>>(xh, w1t1, b1, 1, FFDIM, DMODEL, h1);
    cudaEventRecord(ev_e1g1, s1);

    transpose_cvt_h<<<tg2, tb>>>(w2, w2t0, 0, FFDIM, DMODEL);
    transpose_cvt_h<<<tg2, tb>>>(w2, w2t1, 1, FFDIM, DMODEL);

    moe_gemm_h<0, 128><<<gg1, blk, SMEM_G1>>>(xh, w1t0, b1, 0, FFDIM, DMODEL, h0);
    moe_gemm_h<1, 64><<<gg2, blk, SMEM_G2>>>(h0, w2t0, b2, 0, DMODEL, FFDIM, out);

    // join: expert1 GEMM2 needs h1 (s1) and out (stream 0)
    cudaStreamWaitEvent(0, ev_e1g1, 0);
    moe_gemm_h<2, 64><<<gg2, blk, SMEM_G2>>>(h1, w2t1, b2, 1, DMODEL, FFDIM, out);
}

// round 14
// speedup vs baseline: 1.0925x; 1.0925x over previous
#include <cuda_runtime.h>
#include <cuda_fp16.h>
#include <cstdint>

// Problem constants (B=2, S=4096, D=2048, E=8, DFF=8192, TOP_K=2)
#define NTOK   8192
#define DMODEL 2048
#define NEXP   8
#define FFDIM  8192
#define TOPK   2

// ---------------- device scratch (allocation-free rule: __device__ globals) --
__device__ float  g_logits[NTOK * NEXP];
__device__ float  g_sums[NEXP];
__device__ int    g_sel[TOPK];
__device__ float  g_rw[NTOK * TOPK];
__device__ __half g_xh[(size_t)NTOK * DMODEL];        // x  fp16 [M,K]
__device__ __half g_hh[(size_t)NTOK * FFDIM];         // h  fp16 [M,K]
__device__ __half g_w1t[2][(size_t)FFDIM * DMODEL];   // w1^T fp16 [N=FF, K=D]
__device__ __half g_w2t[2][(size_t)DMODEL * FFDIM];   // w2^T fp16 [N=D,  K=FF]

// ---------------- helpers ----------------------------------------------------
__device__ __forceinline__ void cp16(void* smem, const void* gmem) {
    uint32_t s = (uint32_t)__cvta_generic_to_shared(smem);
    asm volatile("cp.async.cg.shared.global [%0], [%1], 16;\n" :: "r"(s), "l"(gmem));
}
__device__ __forceinline__ void cp_commit() {
    asm volatile("cp.async.commit_group;\n" ::: "memory");
}
template <int N>
__device__ __forceinline__ void cp_wait() {
    asm volatile("cp.async.wait_group %0;\n" :: "n"(N) : "memory");
}
__device__ __forceinline__ void ldsm4(uint32_t* r, uint32_t addr) {
    asm volatile("ldmatrix.sync.aligned.m8n8.x4.shared.b16 {%0,%1,%2,%3}, [%4];"
                 : "=r"(r[0]), "=r"(r[1]), "=r"(r[2]), "=r"(r[3]) : "r"(addr));
}

// ---------------- routing kernels -------------------------------------------
__global__ void router_kernel(const float* __restrict__ x,
                              const float* __restrict__ gw) {
    int n = blockIdx.x;
    const float* xr = x + (size_t)n * DMODEL;
    float acc[NEXP];
#pragma unroll
    for (int e = 0; e < NEXP; e++) acc[e] = 0.f;
    for (int d = threadIdx.x; d < DMODEL; d += 256) {
        float xv = xr[d];
#pragma unroll
        for (int e = 0; e < NEXP; e++)
            acc[e] = fmaf(xv, gw[e * DMODEL + d], acc[e]);
    }
#pragma unroll
    for (int e = 0; e < NEXP; e++)
#pragma unroll
        for (int off = 16; off; off >>= 1)
            acc[e] += __shfl_xor_sync(0xffffffffu, acc[e], off);

    __shared__ float red[NEXP][8];
    int w = threadIdx.x >> 5, lane = threadIdx.x & 31;
    if (lane == 0) {
#pragma unroll
        for (int e = 0; e < NEXP; e++) red[e][w] = acc[e];
    }
    __syncthreads();
    if (threadIdx.x < NEXP) {
        float s = 0.f;
#pragma unroll
        for (int ww = 0; ww < 8; ww++) s += red[threadIdx.x][ww];
        g_logits[n * NEXP + threadIdx.x] = s;
    }
}

__global__ void sum_kernel() {
    int e = blockIdx.x;
    float s = 0.f;
    for (int n = threadIdx.x; n < NTOK; n += blockDim.x)
        s += g_logits[n * NEXP + e];
    __shared__ float sm[256];
    sm[threadIdx.x] = s;
    __syncthreads();
    for (int off = 128; off; off >>= 1) {
        if (threadIdx.x < off) sm[threadIdx.x] += sm[threadIdx.x + off];
        __syncthreads();
    }
    if (threadIdx.x == 0) g_sums[e] = sm[0];
}

__global__ void topk_kernel() {
    if (threadIdx.x == 0) {
        int b = 0;
        for (int i = 1; i < NEXP; i++)
            if (g_sums[i] > g_sums[b]) b = i;     // strict > : lower idx on tie
        int s = (b == 0) ? 1 : 0;
        for (int i = 0; i < NEXP; i++)
            if (i != b && g_sums[i] > g_sums[s]) s = i;
        g_sel[0] = b;
        g_sel[1] = s;
    }
}

__global__ void rw_kernel() {
    int n = blockIdx.x * blockDim.x + threadIdx.x;
    if (n >= NTOK) return;
    int s0 = g_sel[0], s1 = g_sel[1];
    float l0 = g_logits[n * NEXP + s0];
    float l1 = g_logits[n * NEXP + s1];
    float m  = fmaxf(l0, l1);
    float e0 = expf(l0 - m), e1 = expf(l1 - m);
    float inv = 1.0f / (e0 + e1);
    g_rw[n * TOPK + 0] = e0 * inv;
    g_rw[n * TOPK + 1] = e1 * inv;
}

// zero-init the fp32 output (atomic accumulation target)
__global__ void zero_out_kernel(float4* __restrict__ dst, size_t n4) {
    size_t i = (size_t)blockIdx.x * blockDim.x + threadIdx.x;
    if (i < n4) dst[i] = make_float4(0.f, 0.f, 0.f, 0.f);
}

// fp32 -> fp16 straight convert (x)
__global__ void cvt_x_h(const float4* __restrict__ src,
                        __half2* __restrict__ dst, size_t n4) {
    for (size_t i = (size_t)blockIdx.x * blockDim.x + threadIdx.x; i < n4;
         i += (size_t)gridDim.x * blockDim.x) {
        float4 v = src[i];
        dst[i * 2 + 0] = __floats2half2_rn(v.x, v.y);
        dst[i * 2 + 1] = __floats2half2_rn(v.z, v.w);
    }
}

// Transpose + fp16-convert selected expert weight: in [K,N] fp32 -> out [N,K] fp16
__global__ void transpose_cvt_h(const float* __restrict__ Wall,
                                __half* __restrict__ out,
                                int kidx, int K, int N) {
    __shared__ float t[32][33];
    int e = g_sel[kidx];
    const float* src = Wall + (size_t)e * K * N;
    int n0 = blockIdx.x * 32, k0 = blockIdx.y * 32;
#pragma unroll
    for (int i = threadIdx.y; i < 32; i += 8)
        t[i][threadIdx.x] = src[(size_t)(k0 + i) * N + n0 + threadIdx.x];
    __syncthreads();
#pragma unroll
    for (int i = threadIdx.y; i < 32; i += 8)
        out[(size_t)(n0 + i) * K + k0 + threadIdx.x] = __float2half_rn(t[threadIdx.x][i]);
}

// ---------------- fp16 GEMM: 128x256 CTA, 64x64 warp, ldmatrix + cp.async ----
#define BM 128
#define BN 256
#define BK 32
#define ASTRH 40    // halves per row (BK+8): 80B stride; 16B-aligned, ldsm conflict-free
#define BSTRH 40
#define NSTAGE 4
#define A_TILE_H (BM * ASTRH)              // halves
#define B_TILE_H (BN * BSTRH)
#define SMEM_BYTES (NSTAGE * (A_TILE_H + B_TILE_H) * 2)

__device__ __forceinline__ void mma_f16(float* c, const uint32_t* a, const uint32_t* b) {
    asm volatile(
        "mma.sync.aligned.m16n8k16.row.col.f32.f16.f16.f32 "
        "{%0,%1,%2,%3}, {%4,%5,%6,%7}, {%8,%9}, {%0,%1,%2,%3};\n"
        : "+f"(c[0]), "+f"(c[1]), "+f"(c[2]), "+f"(c[3])
        : "r"(a[0]), "r"(a[1]), "r"(a[2]), "r"(a[3]), "r"(b[0]), "r"(b[1]));
}

__device__ __forceinline__ float gelu_tanh(float x) {
    float x3 = x * x * x;
    float t  = tanhf(0.7978845608028654f * (x + 0.044715f * x3));
    return 0.5f * x * (1.0f + t);
}

// MODE 0: Ch = fp16(gelu(A@B^T + bias))            (h production, C is __half*)
// MODE 3: atomicAdd(Cf, rw[:,kidx]*(A@B^T partial [+ bias if kstart==0]))
//         split-K: blockIdx.z selects K-half.
template <int MODE>
__global__ void __launch_bounds__(256, 1)
moe_gemm_h(const __half* __restrict__ A,      // [M,K] fp16 (full K stride)
           const __half* __restrict__ Bt,     // [N,K] fp16 (full K stride)
           const float* __restrict__ Ball,    // bias table [E,N] fp32
           int kidx, int N, int K, int klen,
           void* __restrict__ Cv) {
    extern __shared__ __half smh[];
    __half* As = smh;                          // NSTAGE * A_TILE_H
    __half* Bs = smh + NSTAGE * A_TILE_H;      // NSTAGE * B_TILE_H

    const int tid  = threadIdx.x;
    const int lane = tid & 31;
    const int wid  = tid >> 5;
    const int g    = lane >> 2;     // 0..7
    const int tg   = lane & 3;      // 0..3
    const int wm   = wid & 1;       // 64 rows each
    const int wn   = wid >> 1;      // 64 cols each
    const int m0   = blockIdx.y * BM;
    const int n0   = blockIdx.x * BN;
    const int kstart = blockIdx.z * klen;

    const int e = g_sel[kidx];
    const float* bias = Ball + (size_t)e * N;
    const bool addb = (kstart == 0);

    // ldmatrix per-lane base byte-offsets (kk = 0)
    const int lr  = lane & 7;
    const int sel = lane >> 3;      // 0..3
    uint32_t aoff[4], boff[4];
#pragma unroll
    for (int mt = 0; mt < 4; mt++) {
        int row = wm * 64 + mt * 16 + (sel & 1) * 8 + lr;
        aoff[mt] = (uint32_t)(row * ASTRH + (sel >> 1) * 8) * 2;
    }
#pragma unroll
    for (int p = 0; p < 4; p++) {
        int nn = wn * 64 + p * 16 + (sel >> 1) * 8 + lr;
        boff[p] = (uint32_t)(nn * BSTRH + (sel & 1) * 8) * 2;
    }
    const uint32_t As_u = (uint32_t)__cvta_generic_to_shared(As);
    const uint32_t Bs_u = (uint32_t)__cvta_generic_to_shared(Bs);

    float acc[4][8][4];
#pragma unroll
    for (int i = 0; i < 4; i++)
#pragma unroll
        for (int j = 0; j < 8; j++)
#pragma unroll
            for (int r = 0; r < 4; r++) acc[i][j][r] = 0.f;

    const int KT = klen / BK;

    auto issue_stage = [&](int s, int kt) {
        const int k0 = kstart + kt * BK;
        __half* as = As + s * A_TILE_H;
        __half* bs = Bs + s * B_TILE_H;
#pragma unroll
        for (int i = 0; i < 2; i++) {              // A: 512 chunks
            int idx = tid + i * 256;
            int r = idx >> 2, ch = idx & 3;
            cp16(&as[r * ASTRH + ch * 8], A + (size_t)(m0 + r) * K + k0 + ch * 8);
        }
#pragma unroll
        for (int i = 0; i < 4; i++) {              // B: 1024 chunks
            int idx = tid + i * 256;
            int r = idx >> 2, ch = idx & 3;
            cp16(&bs[r * BSTRH + ch * 8], Bt + (size_t)(n0 + r) * K + k0 + ch * 8);
        }
    };

    // prologue: stages 0..2
    issue_stage(0, 0); cp_commit();
    if (KT > 1) issue_stage(1, 1);
    cp_commit();
    if (KT > 2) issue_stage(2, 2);
    cp_commit();

    for (int kt = 0; kt < KT; kt++) {
        cp_wait<2>();
        __syncthreads();

        if (kt + 3 < KT) issue_stage((kt + 3) & (NSTAGE - 1), kt + 3);
        cp_commit();

        const uint32_t a_base = As_u + (uint32_t)((kt & (NSTAGE - 1)) * A_TILE_H) * 2;
        const uint32_t b_base = Bs_u + (uint32_t)((kt & (NSTAGE - 1)) * B_TILE_H) * 2;

#pragma unroll
        for (int ks = 0; ks < 2; ks++) {
            const uint32_t ko = ks * 32;          // +16 halves
            uint32_t af[4][4], bq[4][4];
#pragma unroll
            for (int mt = 0; mt < 4; mt++) ldsm4(af[mt], a_base + aoff[mt] + ko);
#pragma unroll
            for (int p = 0; p < 4; p++)  ldsm4(bq[p],  b_base + boff[p] + ko);
#pragma unroll
            for (int mt = 0; mt < 4; mt++)
#pragma unroll
                for (int nt = 0; nt < 8; nt++)
                    mma_f16(acc[mt][nt], af[mt], &bq[nt >> 1][(nt & 1) * 2]);
        }
        // next iteration's __syncthreads() protects the stage being overwritten
    }

    // ---------------- epilogue ----------------
#pragma unroll
    for (int mt = 0; mt < 4; mt++) {
        int r0 = m0 + wm * 64 + mt * 16 + g;
        float w0 = 0.f, w1 = 0.f;
        if (MODE != 0) {
            w0 = g_rw[(size_t)r0 * TOPK + kidx];
            w1 = g_rw[(size_t)(r0 + 8) * TOPK + kidx];
        }
#pragma unroll
        for (int nt = 0; nt < 8; nt++) {
            int cc = n0 + wn * 64 + nt * 8 + tg * 2;
            const float* cr = acc[mt][nt];
            if (MODE == 0) {
                float b0 = bias[cc], b1v = bias[cc + 1];
                float y00 = cr[0] + b0, y01 = cr[1] + b1v;
                float y10 = cr[2] + b0, y11 = cr[3] + b1v;
                __half* C = (__half*)Cv;
                __half2* p0 = (__half2*)(C + (size_t)r0 * N + cc);
                __half2* p1 = (__half2*)(C + (size_t)(r0 + 8) * N + cc);
                *p0 = __floats2half2_rn(gelu_tanh(y00), gelu_tanh(y01));
                *p1 = __floats2half2_rn(gelu_tanh(y10), gelu_tanh(y11));
            } else {
                float b0 = addb ? bias[cc] : 0.f;
                float b1v = addb ? bias[cc + 1] : 0.f;
                float* C = (float*)Cv;
                float* p0 = C + (size_t)r0 * N + cc;
                float* p1 = C + (size_t)(r0 + 8) * N + cc;
                atomicAdd(p0,     w0 * (cr[0] + b0));
                atomicAdd(p0 + 1, w0 * (cr[1] + b1v));
                atomicAdd(p1,     w1 * (cr[2] + b0));
                atomicAdd(p1 + 1, w1 * (cr[3] + b1v));
            }
        }
    }
}

// ---------------- launch -----------------------------------------------------
extern "C" void kernel_launch(void* const* d_in, const int* in_sizes, int n_in,
                              void* d_out, int out_size) {
    const float* x  = (const float*)d_in[0];   // [8192,2048]
    const float* gw = (const float*)d_in[1];   // [8,2048]
    const float* w1 = (const float*)d_in[2];   // [8,2048,8192]
    const float* b1 = (const float*)d_in[3];   // [8,8192]
    const float* w2 = (const float*)d_in[4];   // [8,8192,2048]
    const float* b2 = (const float*)d_in[5];   // [8,2048]
    float* out = (float*)d_out;                // [8192,2048]

    __half *xh, *hh, *w1t0, *w2t0;
    cudaGetSymbolAddress((void**)&xh,   g_xh);
    cudaGetSymbolAddress((void**)&hh,   g_hh);
    cudaGetSymbolAddress((void**)&w1t0, g_w1t);
    cudaGetSymbolAddress((void**)&w2t0, g_w2t);
    __half* w1t1 = w1t0 + (size_t)FFDIM * DMODEL;
    __half* w2t1 = w2t0 + (size_t)DMODEL * FFDIM;

    cudaFuncSetAttribute(moe_gemm_h<0>, cudaFuncAttributeMaxDynamicSharedMemorySize, SMEM_BYTES);
    cudaFuncSetAttribute(moe_gemm_h<3>, cudaFuncAttributeMaxDynamicSharedMemorySize, SMEM_BYTES);

    // zero the atomic-accumulation output first (independent of routing)
    size_t on4 = ((size_t)NTOK * DMODEL) >> 2;
    zero_out_kernel<<<(unsigned)((on4 + 255) / 256), 256>>>((float4*)out, on4);

    router_kernel<<<NTOK, 256>>>(x, gw);
    sum_kernel<<<NEXP, 256>>>();
    topk_kernel<<<1, 32>>>();
    rw_kernel<<<NTOK / 256, 256>>>();

    // operand pre-passes: x -> fp16; selected weights -> transposed fp16 [N,K]
    cvt_x_h<<<2048, 256>>>((const float4*)x, (__half2*)xh, ((size_t)NTOK * DMODEL) >> 2);
    dim3 tb(32, 8);
    dim3 tg1(FFDIM / 32, DMODEL / 32);   // w1: K=2048, N=8192
    dim3 tg2(DMODEL / 32, FFDIM / 32);   // w2: K=8192, N=2048
    transpose_cvt_h<<<tg1, tb>>>(w1, w1t0, 0, DMODEL, FFDIM);
    transpose_cvt_h<<<tg1, tb>>>(w1, w1t1, 1, DMODEL, FFDIM);
    transpose_cvt_h<<<tg2, tb>>>(w2, w2t0, 0, FFDIM, DMODEL);
    transpose_cvt_h<<<tg2, tb>>>(w2, w2t1, 1, FFDIM, DMODEL);

    dim3 blk(256);
    dim3 g1(FFDIM / BN, NTOK / BM);      // (32,64)   GEMM1
    dim3 g2(DMODEL / BN, NTOK / BM, 2);  // (8,64,2)  GEMM2 split-K
    const int KH = FFDIM / 2;            // 4096 per K-half

    moe_gemm_h<0><<<g1, blk, SMEM_BYTES>>>(xh, w1t0, b1, 0, FFDIM,  DMODEL, DMODEL, hh);
    moe_gemm_h<3><<<g2, blk, SMEM_BYTES>>>(hh, w2t0, b2, 0, DMODEL, FFDIM,  KH,     out);
    moe_gemm_h<0><<<g1, blk, SMEM_BYTES>>>(xh, w1t1, b1, 1, FFDIM,  DMODEL, DMODEL, hh);
    moe_gemm_h<3><<<g2, blk, SMEM_BYTES>>>(hh, w2t1, b2, 1, DMODEL, FFDIM,  KH,     out);
}